// round 5
// baseline (speedup 1.0000x reference)
#include <cuda_runtime.h>
#include <math.h>

#define IN_DIM   256
#define OUT_DIM  64
#define NUM_HEADS 8
#define BATCH    8
#define SEQ      1024
#define QKV_COLS (OUT_DIM * NUM_HEADS)   // 512
#define ROWS     (BATCH * SEQ)           // 8192

typedef unsigned long long u64;

__device__ float g_Q[ROWS * QKV_COLS];
__device__ float g_K[ROWS * QKV_COLS];
__device__ float g_V[ROWS * QKV_COLS];
__device__ float g_kmax[BATCH * NUM_HEADS];

// ---- packed fp32x2 helpers (FFMA2 path, only reachable via PTX) ----
__device__ __forceinline__ u64 ffma2(u64 a, u64 b, u64 c) {
    u64 d;
    asm("fma.rn.f32x2 %0, %1, %2, %3;" : "=l"(d) : "l"(a), "l"(b), "l"(c));
    return d;
}
__device__ __forceinline__ float2 unpk(u64 x) {
    float2 f;
    asm("mov.b64 {%0, %1}, %2;" : "=f"(f.x), "=f"(f.y) : "l"(x));
    return f;
}

// ---------------------------------------------------------------------------
// Kernel 1: QKV projection. 128x128 tile, 8x8/thread via FFMA2 (8x4 packed).
// A stored DUPLICATED in smem (As2[k][2m]=(a,a)) so the broadcast operand is a
// single LDS.64; B natural so column pairs pack from LDS.128.
// ---------------------------------------------------------------------------
#define ASTR 264    // 2*128 + 8 pad
#define BSTR 132

__global__ __launch_bounds__(256, 2)
void qkv_gemm_kernel(const float* __restrict__ h,
                     const float* __restrict__ Wq, const float* __restrict__ bq,
                     const float* __restrict__ Wk, const float* __restrict__ bk,
                     const float* __restrict__ Wv, const float* __restrict__ bv)
{
    const int which = blockIdx.z;
    const float* __restrict__ W    = (which == 0) ? Wq : (which == 1) ? Wk : Wv;
    const float* __restrict__ bias = (which == 0) ? bq : (which == 1) ? bk : bv;
    float* __restrict__ out        = (which == 0) ? g_Q : (which == 1) ? g_K : g_V;

    __shared__ float As2[2][16][ASTR];
    __shared__ float Bs[2][16][BSTR];

    const int tid = threadIdx.x;
    const int tx = tid & 15;
    const int ty = tid >> 4;
    const int row0 = blockIdx.y * 128;
    const int col0 = blockIdx.x * 128;

    float4 a_reg[2], b_reg[2];
    auto ldg_tile = [&](int k0) {
        #pragma unroll
        for (int it = 0; it < 2; it++) {
            int lin = it * 256 + tid;
            int r  = lin >> 2;
            int kc = (lin & 3) * 4;
            a_reg[it] = *(const float4*)&h[(size_t)(row0 + r) * IN_DIM + k0 + kc];
            int r2 = lin >> 5;
            int c  = (lin & 31) * 4;
            b_reg[it] = *(const float4*)&W[(size_t)(k0 + r2) * QKV_COLS + col0 + c];
        }
    };
    auto sts_tile = [&](int buf) {
        #pragma unroll
        for (int it = 0; it < 2; it++) {
            int lin = it * 256 + tid;
            int r  = lin >> 2;
            int kc = (lin & 3) * 4;
            float4 a = a_reg[it];
            *(float2*)&As2[buf][kc + 0][2 * r] = make_float2(a.x, a.x);
            *(float2*)&As2[buf][kc + 1][2 * r] = make_float2(a.y, a.y);
            *(float2*)&As2[buf][kc + 2][2 * r] = make_float2(a.z, a.z);
            *(float2*)&As2[buf][kc + 3][2 * r] = make_float2(a.w, a.w);
            int r2 = lin >> 5;
            int c  = (lin & 31) * 4;
            *(float4*)&Bs[buf][r2][c] = b_reg[it];
        }
    };

    u64 acc2[8][4] = {};     // rows i, packed col pairs (2jp, 2jp+1)

    ldg_tile(0);
    sts_tile(0);
    __syncthreads();

    for (int kt = 0; kt < 16; kt++) {
        if (kt < 15) ldg_tile((kt + 1) * 16);
        const int buf = kt & 1;
        #pragma unroll
        for (int kk = 0; kk < 16; kk++) {
            ulonglong2 b0 = *(const ulonglong2*)&Bs[buf][kk][tx * 8];
            ulonglong2 b1 = *(const ulonglong2*)&Bs[buf][kk][tx * 8 + 4];
            u64 bj[4] = {b0.x, b0.y, b1.x, b1.y};
            #pragma unroll
            for (int i = 0; i < 8; i++) {
                u64 ad = *(const u64*)&As2[buf][kk][ty * 16 + 2 * i];
                #pragma unroll
                for (int jp = 0; jp < 4; jp++)
                    acc2[i][jp] = ffma2(ad, bj[jp], acc2[i][jp]);
            }
        }
        if (kt < 15) sts_tile((kt + 1) & 1);
        __syncthreads();
    }

    const int cbase = col0 + tx * 8;
    float4 bv0 = *(const float4*)&bias[cbase];
    float4 bv1 = *(const float4*)&bias[cbase + 4];
    #pragma unroll
    for (int i = 0; i < 8; i++) {
        int r = row0 + ty * 8 + i;
        float2 p0 = unpk(acc2[i][0]), p1 = unpk(acc2[i][1]);
        float2 p2 = unpk(acc2[i][2]), p3 = unpk(acc2[i][3]);
        float4 o0 = make_float4(p0.x + bv0.x, p0.y + bv0.y, p1.x + bv0.z, p1.y + bv0.w);
        float4 o1 = make_float4(p2.x + bv1.x, p2.y + bv1.y, p3.x + bv1.z, p3.y + bv1.w);
        *(float4*)&out[(size_t)r * QKV_COLS + cbase]     = o0;
        *(float4*)&out[(size_t)r * QKV_COLS + cbase + 4] = o1;
    }
}

// ---------------------------------------------------------------------------
// Kernel 1b: max_k |k|^2 per (batch, head).
// ---------------------------------------------------------------------------
__global__ __launch_bounds__(256)
void kmax_kernel()
{
    const int bh = blockIdx.x;
    const float* __restrict__ K =
        g_K + ((size_t)(bh >> 3) * SEQ) * QKV_COLS + (bh & 7) * OUT_DIM;

    float mx = 0.f;
    for (int r = threadIdx.x; r < SEQ; r += 256) {
        const float4* row = (const float4*)&K[(size_t)r * QKV_COLS];
        float ss = 0.f;
        #pragma unroll
        for (int j = 0; j < 16; j++) {
            float4 v = row[j];
            ss = fmaf(v.x, v.x, ss); ss = fmaf(v.y, v.y, ss);
            ss = fmaf(v.z, v.z, ss); ss = fmaf(v.w, v.w, ss);
        }
        mx = fmaxf(mx, ss);
    }
    #pragma unroll
    for (int off = 16; off >= 1; off >>= 1)
        mx = fmaxf(mx, __shfl_xor_sync(0xffffffffu, mx, off));
    __shared__ float wmx[8];
    if ((threadIdx.x & 31) == 0) wmx[threadIdx.x >> 5] = mx;
    __syncthreads();
    if (threadIdx.x == 0) {
        float m = wmx[0];
        #pragma unroll
        for (int w = 1; w < 8; w++) m = fmaxf(m, wmx[w]);
        g_kmax[bh] = m;
    }
}

// ---------------------------------------------------------------------------
// Kernel 2: fused masked attention, static-max softmax, FFMA2 everywhere.
// BR=64, BC=64, 256 threads, 4x4 per thread (2 packed row-pairs x 4 / 4 x 2 pairs).
// K and P stored duplicated in smem; Q/V packed natural.
// ---------------------------------------------------------------------------
#define BR 64
#define BC 64
#define QSTR 68
#define KSTR 136     // 2*64 + 8 pad (dup layouts)
#define CSTR 68

__global__ __launch_bounds__(256, 2)
void attn_kernel(const int* __restrict__ adj, float* __restrict__ out)
{
    extern __shared__ float smem[];
    float* Qt   = smem;                    // [64][QSTR]  Qt[d][r]
    float* Kt2  = Qt  + 64 * QSTR;         // [64][KSTR]  Kt2[d][2c] duplicated
    float* Vs   = Kt2 + 64 * KSTR;         // [64][CSTR]  Vs[c][d]
    float* Ps2  = Vs  + 64 * CSTR;         // [64][KSTR]  Ps2[r][2c] duplicated
    float* Mrow = Ps2 + 64 * KSTR;         // [64]

    const int b  = blockIdx.z;
    const int hd = blockIdx.y;
    const int q0 = blockIdx.x * BR;

    const int tid = threadIdx.x;
    const int tx = tid & 15;               // col group (4 keys / 4 dims)
    const int ty = tid >> 4;               // row group (4 queries)

    const float* __restrict__ Q = g_Q + ((size_t)b * SEQ) * QKV_COLS + hd * OUT_DIM;
    const float* __restrict__ K = g_K + ((size_t)b * SEQ) * QKV_COLS + hd * OUT_DIM;
    const float* __restrict__ V = g_V + ((size_t)b * SEQ) * QKV_COLS + hd * OUT_DIM;

    // ---- prologue: Q tile transposed ----
    #pragma unroll
    for (int it = 0; it < 4; it++) {
        int lin = it * 256 + tid;          // 0..1023
        int r = lin >> 4;                  // 0..63
        int d = (lin & 15) * 4;
        float4 q = *(const float4*)&Q[(size_t)(q0 + r) * QKV_COLS + d];
        Qt[(d + 0) * QSTR + r] = q.x;
        Qt[(d + 1) * QSTR + r] = q.y;
        Qt[(d + 2) * QSTR + r] = q.z;
        Qt[(d + 3) * QSTR + r] = q.w;
    }
    __syncthreads();

    const float kmax2 = g_kmax[b * NUM_HEADS + hd];
    if (tid < 64) {
        float ss = 0.f;
        #pragma unroll 16
        for (int d = 0; d < 64; d++) {
            float q = Qt[d * QSTR + tid];
            ss = fmaf(q, q, ss);
        }
        Mrow[tid] = sqrtf(ss * kmax2) * 0.125f;
    }
    __syncthreads();

    const float scale = 0.125f;
    const float NEG = -1.0e30f;

    float l[4];
    float m_i[4];
    u64 o2[4][2] = {};                     // [row i][packed dim pair]
    #pragma unroll
    for (int i = 0; i < 4; i++) { l[i] = 0.f; m_i[i] = Mrow[ty * 4 + i]; }

    for (int t = 0; t < SEQ / BC; t++) {
        const int m0 = t * BC;

        // ---- load K (duplicated) + V (natural) ----
        #pragma unroll
        for (int it = 0; it < 4; it++) {
            int lin = it * 256 + tid;
            int r = lin >> 4;
            int d = (lin & 15) * 4;
            float4 k = *(const float4*)&K[(size_t)(m0 + r) * QKV_COLS + d];
            *(float2*)&Kt2[(d + 0) * KSTR + 2 * r] = make_float2(k.x, k.x);
            *(float2*)&Kt2[(d + 1) * KSTR + 2 * r] = make_float2(k.y, k.y);
            *(float2*)&Kt2[(d + 2) * KSTR + 2 * r] = make_float2(k.z, k.z);
            *(float2*)&Kt2[(d + 3) * KSTR + 2 * r] = make_float2(k.w, k.w);
            float4 v = *(const float4*)&V[(size_t)(m0 + r) * QKV_COLS + d];
            *(float4*)&Vs[r * CSTR + d] = v;
        }
        __syncthreads();

        // ---- S = Q K^T : packed row pairs x dup'd key cols ----
        u64 s2[2][4] = {};
        #pragma unroll 8
        for (int kk = 0; kk < 64; kk++) {
            ulonglong2 qp = *(const ulonglong2*)&Qt[kk * QSTR + ty * 4];
            ulonglong2 ka = *(const ulonglong2*)&Kt2[kk * KSTR + tx * 8];
            ulonglong2 kb = *(const ulonglong2*)&Kt2[kk * KSTR + tx * 8 + 4];
            s2[0][0] = ffma2(qp.x, ka.x, s2[0][0]);
            s2[0][1] = ffma2(qp.x, ka.y, s2[0][1]);
            s2[0][2] = ffma2(qp.x, kb.x, s2[0][2]);
            s2[0][3] = ffma2(qp.x, kb.y, s2[0][3]);
            s2[1][0] = ffma2(qp.y, ka.x, s2[1][0]);
            s2[1][1] = ffma2(qp.y, ka.y, s2[1][1]);
            s2[1][2] = ffma2(qp.y, kb.x, s2[1][2]);
            s2[1][3] = ffma2(qp.y, kb.y, s2[1][3]);
        }

        // unpack scores: s[i][j]
        float s[4][4];
        #pragma unroll
        for (int j = 0; j < 4; j++) {
            float2 t0 = unpk(s2[0][j]);
            float2 t1 = unpk(s2[1][j]);
            s[0][j] = t0.x; s[1][j] = t0.y;
            s[2][j] = t1.x; s[3][j] = t1.y;
        }

        // ---- mask + exp + partial l + stage P duplicated ----
        #pragma unroll
        for (int i = 0; i < 4; i++) {
            const float m = m_i[i];
            int4 a4 = *(const int4*)&adj[(size_t)(q0 + ty * 4 + i) * SEQ + m0 + tx * 4];
            float p0 = __expf(fmaf(a4.x ? s[i][0] : NEG, scale, -m));
            float p1 = __expf(fmaf(a4.y ? s[i][1] : NEG, scale, -m));
            float p2 = __expf(fmaf(a4.z ? s[i][2] : NEG, scale, -m));
            float p3 = __expf(fmaf(a4.w ? s[i][3] : NEG, scale, -m));
            l[i] += (p0 + p1) + (p2 + p3);
            float* pr = &Ps2[(ty * 4 + i) * KSTR + tx * 8];
            *(float4*)(pr)     = make_float4(p0, p0, p1, p1);
            *(float4*)(pr + 4) = make_float4(p2, p2, p3, p3);
        }
        __syncthreads();

        // ---- O += P V : dup'd P scalars x packed V dim pairs ----
        #pragma unroll 4
        for (int c = 0; c < BC; c++) {
            ulonglong2 vv = *(const ulonglong2*)&Vs[c * CSTR + tx * 4];
            #pragma unroll
            for (int i = 0; i < 4; i++) {
                u64 pd = *(const u64*)&Ps2[(ty * 4 + i) * KSTR + 2 * c];
                o2[i][0] = ffma2(pd, vv.x, o2[i][0]);
                o2[i][1] = ffma2(pd, vv.y, o2[i][1]);
            }
        }
        __syncthreads();
    }

    // ---- epilogue: reduce l across 16 lanes, normalize, store ----
    #pragma unroll
    for (int i = 0; i < 4; i++) {
        float li = l[i];
        #pragma unroll
        for (int off = 8; off >= 1; off >>= 1)
            li += __shfl_xor_sync(0xffffffffu, li, off);
        float inv = 1.0f / li;
        int n = q0 + ty * 4 + i;
        float2 oa = unpk(o2[i][0]);
        float2 ob = unpk(o2[i][1]);
        float4 o = make_float4(oa.x * inv, oa.y * inv, ob.x * inv, ob.y * inv);
        *(float4*)&out[((size_t)(b * SEQ + n)) * QKV_COLS + hd * OUT_DIM + tx * 4] = o;
    }
}

// ---------------------------------------------------------------------------
// Launch
// ---------------------------------------------------------------------------
extern "C" void kernel_launch(void* const* d_in, const int* in_sizes, int n_in,
                              void* d_out, int out_size)
{
    const int*   adj = (const int*)  d_in[0];
    const float* h   = (const float*)d_in[1];
    const float* Wq  = (const float*)d_in[2];
    const float* bq  = (const float*)d_in[3];
    const float* Wk  = (const float*)d_in[4];
    const float* bk  = (const float*)d_in[5];
    const float* Wv  = (const float*)d_in[6];
    const float* bv  = (const float*)d_in[7];
    float* out = (float*)d_out;

    qkv_gemm_kernel<<<dim3(4, 64, 3), 256>>>(h, Wq, bq, Wk, bk, Wv, bv);
    kmax_kernel<<<64, 256>>>();

    const int smem_bytes = (64 * QSTR + 64 * KSTR + 64 * CSTR + 64 * KSTR + 64)
                           * (int)sizeof(float);   // 104,704 B
    static bool attr_set = false;
    if (!attr_set) {
        cudaFuncSetAttribute(attn_kernel,
                             cudaFuncAttributeMaxDynamicSharedMemorySize, smem_bytes);
        attr_set = true;
    }
    attn_kernel<<<dim3(SEQ / BR, NUM_HEADS, BATCH), 256, smem_bytes>>>(adj, out);
}

// round 7
// speedup vs baseline: 3.6871x; 3.6871x over previous
#include <cuda_runtime.h>
#include <cuda_bf16.h>
#include <math.h>
#include <stdint.h>

#define IN_DIM   256
#define OUT_DIM  64
#define NUM_HEADS 8
#define BATCH    8
#define SEQ      1024
#define QKV_COLS (OUT_DIM * NUM_HEADS)   // 512
#define ROWS     (BATCH * SEQ)           // 8192

// bf16 hi/lo split Q/K/V (Q pre-scaled by 0.125)
__device__ __nv_bfloat16 g_Qh[ROWS * QKV_COLS];
__device__ __nv_bfloat16 g_Ql[ROWS * QKV_COLS];
__device__ __nv_bfloat16 g_Kh[ROWS * QKV_COLS];
__device__ __nv_bfloat16 g_Kl[ROWS * QKV_COLS];
__device__ __nv_bfloat16 g_Vh[ROWS * QKV_COLS];
__device__ __nv_bfloat16 g_Vl[ROWS * QKV_COLS];
__device__ float g_kmax[BATCH * NUM_HEADS];

// ---------------------------------------------------------------------------
// helpers
// ---------------------------------------------------------------------------
__device__ __forceinline__ uint32_t smem_u32(const void* p) {
    uint32_t a;
    asm("{ .reg .u64 t; cvta.to.shared.u64 t, %1; cvt.u32.u64 %0, t; }"
        : "=r"(a) : "l"(p));
    return a;
}
__device__ __forceinline__ uint32_t pack_bf2(float a, float b) {
    __nv_bfloat162 t = __floats2bfloat162_rn(a, b);
    return *reinterpret_cast<uint32_t*>(&t);
}
__device__ __forceinline__ float bf_hi(float x) {
    return __bfloat162float(__float2bfloat16_rn(x));
}
__device__ __forceinline__ float2 bf2f(uint32_t u) {
    __nv_bfloat162 b = *reinterpret_cast<__nv_bfloat162*>(&u);
    return __bfloat1622float2(b);
}
__device__ __forceinline__ void ldsm_x4(uint32_t* r, uint32_t addr) {
    asm volatile("ldmatrix.sync.aligned.m8n8.x4.shared.b16 {%0,%1,%2,%3}, [%4];"
        : "=r"(r[0]), "=r"(r[1]), "=r"(r[2]), "=r"(r[3]) : "r"(addr));
}
__device__ __forceinline__ void ldsm_x4_t(uint32_t* r, uint32_t addr) {
    asm volatile("ldmatrix.sync.aligned.m8n8.x4.trans.shared.b16 {%0,%1,%2,%3}, [%4];"
        : "=r"(r[0]), "=r"(r[1]), "=r"(r[2]), "=r"(r[3]) : "r"(addr));
}
__device__ __forceinline__ void mma16816(float* d, const uint32_t* a,
                                         uint32_t b0, uint32_t b1) {
    asm volatile("mma.sync.aligned.m16n8k16.row.col.f32.bf16.bf16.f32 "
        "{%0,%1,%2,%3}, {%4,%5,%6,%7}, {%8,%9}, {%0,%1,%2,%3};"
        : "+f"(d[0]), "+f"(d[1]), "+f"(d[2]), "+f"(d[3])
        : "r"(a[0]), "r"(a[1]), "r"(a[2]), "r"(a[3]), "r"(b0), "r"(b1));
}

// ---------------------------------------------------------------------------
// Kernel 1: QKV projection (fp32 compute), epilogue splits to bf16 hi/lo.
// Q is pre-scaled by 0.125 (= 1/sqrt(64)).
// ---------------------------------------------------------------------------
__global__ __launch_bounds__(256, 2)
void qkv_gemm_kernel(const float* __restrict__ h,
                     const float* __restrict__ Wq, const float* __restrict__ bq,
                     const float* __restrict__ Wk, const float* __restrict__ bk,
                     const float* __restrict__ Wv, const float* __restrict__ bv)
{
    const int which = blockIdx.z;
    const float* __restrict__ W    = (which == 0) ? Wq : (which == 1) ? Wk : Wv;
    const float* __restrict__ bias = (which == 0) ? bq : (which == 1) ? bk : bv;
    __nv_bfloat16* __restrict__ Oh = (which == 0) ? g_Qh : (which == 1) ? g_Kh : g_Vh;
    __nv_bfloat16* __restrict__ Ol = (which == 0) ? g_Ql : (which == 1) ? g_Kl : g_Vl;
    const float sc = (which == 0) ? 0.125f : 1.0f;

    __shared__ float As[16][132];
    __shared__ float Bs[16][132];

    const int tid = threadIdx.x;
    const int tx = tid & 15;
    const int ty = tid >> 4;
    const int row0 = blockIdx.y * 128;
    const int col0 = blockIdx.x * 128;

    float acc[8][8] = {};

    for (int k0 = 0; k0 < IN_DIM; k0 += 16) {
        #pragma unroll
        for (int it = 0; it < 2; it++) {
            int lin = it * 256 + tid;
            int r  = lin >> 2;
            int kc = (lin & 3) * 4;
            float4 a = *(const float4*)&h[(size_t)(row0 + r) * IN_DIM + k0 + kc];
            As[kc + 0][r] = a.x;
            As[kc + 1][r] = a.y;
            As[kc + 2][r] = a.z;
            As[kc + 3][r] = a.w;
            int r2 = lin >> 5;
            int c  = (lin & 31) * 4;
            *(float4*)&Bs[r2][c] =
                *(const float4*)&W[(size_t)(k0 + r2) * QKV_COLS + col0 + c];
        }
        __syncthreads();

        #pragma unroll
        for (int kk = 0; kk < 16; kk++) {
            float4 a0 = *(const float4*)&As[kk][ty * 8];
            float4 a1 = *(const float4*)&As[kk][ty * 8 + 4];
            float4 b0 = *(const float4*)&Bs[kk][tx * 8];
            float4 b1 = *(const float4*)&Bs[kk][tx * 8 + 4];
            float am[8] = {a0.x, a0.y, a0.z, a0.w, a1.x, a1.y, a1.z, a1.w};
            float bn[8] = {b0.x, b0.y, b0.z, b0.w, b1.x, b1.y, b1.z, b1.w};
            #pragma unroll
            for (int i = 0; i < 8; i++)
                #pragma unroll
                for (int j = 0; j < 8; j++)
                    acc[i][j] = fmaf(am[i], bn[j], acc[i][j]);
        }
        __syncthreads();
    }

    const int cbase = col0 + tx * 8;
    float bb[8];
    #pragma unroll
    for (int j = 0; j < 8; j++) bb[j] = bias[cbase + j];

    #pragma unroll
    for (int i = 0; i < 8; i++) {
        int r = row0 + ty * 8 + i;
        float v[8];
        #pragma unroll
        for (int j = 0; j < 8; j++) v[j] = (acc[i][j] + bb[j]) * sc;
        uint32_t hi[4], lo[4];
        #pragma unroll
        for (int jp = 0; jp < 4; jp++) {
            float a = v[2 * jp], c = v[2 * jp + 1];
            float ah = bf_hi(a), ch = bf_hi(c);
            hi[jp] = pack_bf2(ah, ch);
            lo[jp] = pack_bf2(a - ah, c - ch);
        }
        *(uint4*)&Oh[(size_t)r * QKV_COLS + cbase] = *(uint4*)hi;
        *(uint4*)&Ol[(size_t)r * QKV_COLS + cbase] = *(uint4*)lo;
    }
}

// ---------------------------------------------------------------------------
// Kernel 1b: max_k |k|^2 per (batch, head), from bf16 hi/lo.
// ---------------------------------------------------------------------------
__global__ __launch_bounds__(256)
void kmax_kernel()
{
    const int bh = blockIdx.x;
    const __nv_bfloat16* Kh = g_Kh + ((size_t)(bh >> 3) * SEQ) * QKV_COLS + (bh & 7) * OUT_DIM;
    const __nv_bfloat16* Kl = g_Kl + ((size_t)(bh >> 3) * SEQ) * QKV_COLS + (bh & 7) * OUT_DIM;

    float mx = 0.f;
    for (int r = threadIdx.x; r < SEQ; r += 256) {
        float ss = 0.f;
        #pragma unroll
        for (int c = 0; c < 8; c++) {
            uint4 uh = *(const uint4*)&Kh[(size_t)r * QKV_COLS + c * 8];
            uint4 ul = *(const uint4*)&Kl[(size_t)r * QKV_COLS + c * 8];
            const uint32_t* ph = (const uint32_t*)&uh;
            const uint32_t* pl = (const uint32_t*)&ul;
            #pragma unroll
            for (int q = 0; q < 4; q++) {
                float2 fh = bf2f(ph[q]), fl = bf2f(pl[q]);
                float a = fh.x + fl.x, b = fh.y + fl.y;
                ss = fmaf(a, a, ss); ss = fmaf(b, b, ss);
            }
        }
        mx = fmaxf(mx, ss);
    }
    #pragma unroll
    for (int off = 16; off >= 1; off >>= 1)
        mx = fmaxf(mx, __shfl_xor_sync(0xffffffffu, mx, off));
    __shared__ float wmx[8];
    if ((threadIdx.x & 31) == 0) wmx[threadIdx.x >> 5] = mx;
    __syncthreads();
    if (threadIdx.x == 0) {
        float m = wmx[0];
        #pragma unroll
        for (int w = 1; w < 8; w++) m = fmaxf(m, wmx[w]);
        g_kmax[bh] = m;
    }
}

// ---------------------------------------------------------------------------
// Kernel 2: mma.sync bf16-split flash attention, static max (no rescale).
// Block = (64-query tile, head, batch), 128 threads = 4 warps (16 q-rows each).
// smem tiles stride 72 bf16 (conflict-free ldmatrix).
// ---------------------------------------------------------------------------
#define TSTR 72
#define TILE_E (64 * TSTR)          // elements per tile array

__global__ __launch_bounds__(128, 2)
void attn_mma_kernel(const int* __restrict__ adj, float* __restrict__ out)
{
    extern __shared__ __nv_bfloat16 sm[];
    __nv_bfloat16* sQh = sm;
    __nv_bfloat16* sQl = sQh + TILE_E;
    __nv_bfloat16* sKh = sQl + TILE_E;
    __nv_bfloat16* sKl = sKh + TILE_E;
    __nv_bfloat16* sVh = sKl + TILE_E;
    __nv_bfloat16* sVl = sVh + TILE_E;
    float* sM = (float*)(sVl + TILE_E);   // [64]

    const int b  = blockIdx.z;
    const int hd = blockIdx.y;
    const int q0 = blockIdx.x * 64;
    const int tid  = threadIdx.x;
    const int w    = tid >> 5;
    const int lane = tid & 31;
    const int g  = lane >> 2;
    const int t4 = lane & 3;

    const size_t bN  = (size_t)b * SEQ;
    const int hdo = hd * OUT_DIM;

    // ---- stage Q (hi/lo) ----
    #pragma unroll
    for (int it = 0; it < 4; it++) {
        int lin = it * 128 + tid;          // 0..511
        int r  = lin >> 3;                 // 0..63
        int c8 = (lin & 7) * 8;
        *(uint4*)&sQh[r * TSTR + c8] =
            *(const uint4*)&g_Qh[(bN + q0 + r) * QKV_COLS + hdo + c8];
        *(uint4*)&sQl[r * TSTR + c8] =
            *(const uint4*)&g_Ql[(bN + q0 + r) * QKV_COLS + hdo + c8];
    }
    __syncthreads();

    // ---- static row max: |q_scaled| * |k|_max  (Cauchy-Schwarz) ----
    const float kmax2 = g_kmax[b * NUM_HEADS + hd];
    if (tid < 64) {
        float ss = 0.f;
        #pragma unroll
        for (int c = 0; c < 8; c++) {
            uint4 uh = *(const uint4*)&sQh[tid * TSTR + c * 8];
            uint4 ul = *(const uint4*)&sQl[tid * TSTR + c * 8];
            const uint32_t* ph = (const uint32_t*)&uh;
            const uint32_t* pl = (const uint32_t*)&ul;
            #pragma unroll
            for (int q = 0; q < 4; q++) {
                float2 fh = bf2f(ph[q]), fl = bf2f(pl[q]);
                float a = fh.x + fl.x, c2 = fh.y + fl.y;
                ss = fmaf(a, a, ss); ss = fmaf(c2, c2, ss);
            }
        }
        sM[tid] = sqrtf(ss * kmax2);
    }
    __syncthreads();

    // ---- preload Q fragments (4 d-chunks, hi+lo) ----
    const uint32_t qbase_h = smem_u32(sQh);
    const uint32_t qbase_l = smem_u32(sQl);
    uint32_t qh[4][4], ql[4][4];
    {
        int row = 16 * w + (lane & 7) + 8 * ((lane >> 3) & 1);
        int dof = 8 * (lane >> 4);
        #pragma unroll
        for (int kt = 0; kt < 4; kt++) {
            uint32_t off = (uint32_t)(row * TSTR + 16 * kt + dof) * 2;
            ldsm_x4(qh[kt], qbase_h + off);
            ldsm_x4(ql[kt], qbase_l + off);
        }
    }
    const float mg = sM[16 * w + g];
    const float m2 = sM[16 * w + g + 8];

    const uint32_t kbase_h = smem_u32(sKh);
    const uint32_t kbase_l = smem_u32(sKl);
    const uint32_t vbase_h = smem_u32(sVh);
    const uint32_t vbase_l = smem_u32(sVl);

    float o[8][4] = {};
    float lg = 0.f, l2 = 0.f;

    for (int t = 0; t < SEQ / 64; t++) {
        const int m0 = t * 64;

        // ---- stage K/V (hi/lo) ----
        #pragma unroll
        for (int it = 0; it < 4; it++) {
            int lin = it * 128 + tid;
            int r  = lin >> 3;
            int c8 = (lin & 7) * 8;
            size_t gofs = (bN + m0 + r) * QKV_COLS + hdo + c8;
            int sofs = r * TSTR + c8;
            *(uint4*)&sKh[sofs] = *(const uint4*)&g_Kh[gofs];
            *(uint4*)&sKl[sofs] = *(const uint4*)&g_Kl[gofs];
            *(uint4*)&sVh[sofs] = *(const uint4*)&g_Vh[gofs];
            *(uint4*)&sVl[sofs] = *(const uint4*)&g_Vl[gofs];
        }
        __syncthreads();

        // ---- QK^T: S(16x64 per warp), 3 passes ----
        float pv[8][4];
        const int krow = (lane & 7);
        const int kdof = 8 * (lane >> 3);
        #pragma unroll
        for (int j = 0; j < 8; j++) {
            uint32_t bh[8], bl[8];
            uint32_t roff = (uint32_t)((8 * j + krow) * TSTR + kdof) * 2;
            ldsm_x4(bh + 0, kbase_h + roff);
            ldsm_x4(bh + 4, kbase_h + roff + 64);   // +32 bf16 = 64B
            ldsm_x4(bl + 0, kbase_l + roff);
            ldsm_x4(bl + 4, kbase_l + roff + 64);
            float d[4] = {};
            #pragma unroll
            for (int kt = 0; kt < 4; kt++) {
                int hi2 = kt >> 1, oo = (kt & 1) * 2;
                mma16816(d, qh[kt], bh[4 * hi2 + oo], bh[4 * hi2 + oo + 1]);
            }
            #pragma unroll
            for (int kt = 0; kt < 4; kt++) {
                int hi2 = kt >> 1, oo = (kt & 1) * 2;
                mma16816(d, ql[kt], bh[4 * hi2 + oo], bh[4 * hi2 + oo + 1]);
            }
            #pragma unroll
            for (int kt = 0; kt < 4; kt++) {
                int hi2 = kt >> 1, oo = (kt & 1) * 2;
                mma16816(d, qh[kt], bl[4 * hi2 + oo], bl[4 * hi2 + oo + 1]);
            }
            pv[j][0] = d[0]; pv[j][1] = d[1]; pv[j][2] = d[2]; pv[j][3] = d[3];
        }

        // ---- mask + exp (scores already scaled via Q) ----
        const int r1 = q0 + 16 * w + g;
        #pragma unroll
        for (int j = 0; j < 8; j++) {
            int cc = m0 + 8 * j + 2 * t4;
            int2 a0 = *(const int2*)&adj[(size_t)r1 * SEQ + cc];
            int2 a1 = *(const int2*)&adj[(size_t)(r1 + 8) * SEQ + cc];
            float p0 = a0.x ? __expf(pv[j][0] - mg) : 0.f;
            float p1 = a0.y ? __expf(pv[j][1] - mg) : 0.f;
            float p2 = a1.x ? __expf(pv[j][2] - m2) : 0.f;
            float p3 = a1.y ? __expf(pv[j][3] - m2) : 0.f;
            lg += p0 + p1;
            l2 += p2 + p3;
            pv[j][0] = p0; pv[j][1] = p1; pv[j][2] = p2; pv[j][3] = p3;
        }

        // ---- split P into bf16 hi/lo A-fragments ----
        uint32_t ph[4][4], pl[4][4];
        #pragma unroll
        for (int kt = 0; kt < 4; kt++) {
            const float* e0 = pv[2 * kt];
            const float* e1 = pv[2 * kt + 1];
            float h00 = bf_hi(e0[0]), h01 = bf_hi(e0[1]);
            float h02 = bf_hi(e0[2]), h03 = bf_hi(e0[3]);
            float h10 = bf_hi(e1[0]), h11 = bf_hi(e1[1]);
            float h12 = bf_hi(e1[2]), h13 = bf_hi(e1[3]);
            ph[kt][0] = pack_bf2(h00, h01);
            ph[kt][1] = pack_bf2(h02, h03);
            ph[kt][2] = pack_bf2(h10, h11);
            ph[kt][3] = pack_bf2(h12, h13);
            pl[kt][0] = pack_bf2(e0[0] - h00, e0[1] - h01);
            pl[kt][1] = pack_bf2(e0[2] - h02, e0[3] - h03);
            pl[kt][2] = pack_bf2(e1[0] - h10, e1[1] - h11);
            pl[kt][3] = pack_bf2(e1[2] - h12, e1[3] - h13);
        }

        // ---- PV: O(16x64 per warp) += P V, 3 passes ----
        const int vrow = 8 * (lane >> 3) + (lane & 7);
        #pragma unroll
        for (int j = 0; j < 8; j++) {
            uint32_t bh[8], bl[8];
            uint32_t c2 = (uint32_t)(8 * j) * 2;
            uint32_t r0 = (uint32_t)(vrow * TSTR) * 2 + c2;
            uint32_t r32 = (uint32_t)((vrow + 32) * TSTR) * 2 + c2;
            ldsm_x4_t(bh + 0, vbase_h + r0);
            ldsm_x4_t(bh + 4, vbase_h + r32);
            ldsm_x4_t(bl + 0, vbase_l + r0);
            ldsm_x4_t(bl + 4, vbase_l + r32);
            #pragma unroll
            for (int kt = 0; kt < 4; kt++) {
                int hi2 = kt >> 1, oo = (kt & 1) * 2;
                uint32_t vb0 = bh[4 * hi2 + oo], vb1 = bh[4 * hi2 + oo + 1];
                uint32_t wb0 = bl[4 * hi2 + oo], wb1 = bl[4 * hi2 + oo + 1];
                mma16816(o[j], ph[kt], vb0, vb1);
                mma16816(o[j], pl[kt], vb0, vb1);
                mma16816(o[j], ph[kt], wb0, wb1);
            }
        }
        __syncthreads();
    }

    // ---- epilogue: quad-reduce l, normalize, store ----
    lg += __shfl_xor_sync(0xffffffffu, lg, 1);
    lg += __shfl_xor_sync(0xffffffffu, lg, 2);
    l2 += __shfl_xor_sync(0xffffffffu, l2, 1);
    l2 += __shfl_xor_sync(0xffffffffu, l2, 2);
    const float invg = 1.0f / lg;
    const float inv2 = 1.0f / l2;

    const int r1 = q0 + 16 * w + g;
    #pragma unroll
    for (int j = 0; j < 8; j++) {
        int cc = hdo + 8 * j + 2 * t4;
        *(float2*)&out[(bN + r1) * QKV_COLS + cc] =
            make_float2(o[j][0] * invg, o[j][1] * invg);
        *(float2*)&out[(bN + r1 + 8) * QKV_COLS + cc] =
            make_float2(o[j][2] * inv2, o[j][3] * inv2);
    }
}

// ---------------------------------------------------------------------------
// Launch
// ---------------------------------------------------------------------------
extern "C" void kernel_launch(void* const* d_in, const int* in_sizes, int n_in,
                              void* d_out, int out_size)
{
    const int*   adj = (const int*)  d_in[0];
    const float* h   = (const float*)d_in[1];
    const float* Wq  = (const float*)d_in[2];
    const float* bq  = (const float*)d_in[3];
    const float* Wk  = (const float*)d_in[4];
    const float* bk  = (const float*)d_in[5];
    const float* Wv  = (const float*)d_in[6];
    const float* bv  = (const float*)d_in[7];
    float* out = (float*)d_out;

    qkv_gemm_kernel<<<dim3(4, 64, 3), 256>>>(h, Wq, bq, Wk, bk, Wv, bv);
    kmax_kernel<<<64, 256>>>();

    const int smem_bytes = 6 * TILE_E * 2 + 64 * 4;   // 55,552 B
    static bool attr_set = false;
    if (!attr_set) {
        cudaFuncSetAttribute(attn_mma_kernel,
                             cudaFuncAttributeMaxDynamicSharedMemorySize, smem_bytes);
        attr_set = true;
    }
    attn_mma_kernel<<<dim3(SEQ / 64, NUM_HEADS, BATCH), 128, smem_bytes>>>(adj, out);
}

// round 8
// speedup vs baseline: 4.7000x; 1.2747x over previous
#include <cuda_runtime.h>
#include <cuda_bf16.h>
#include <math.h>
#include <stdint.h>

#define IN_DIM   256
#define OUT_DIM  64
#define NUM_HEADS 8
#define BATCH    8
#define SEQ      1024
#define QKV_COLS (OUT_DIM * NUM_HEADS)   // 512
#define ROWS     (BATCH * SEQ)           // 8192

// bf16 hi/lo split inputs/outputs
__device__ __nv_bfloat16 g_hh[ROWS * IN_DIM];
__device__ __nv_bfloat16 g_hl[ROWS * IN_DIM];
__device__ __nv_bfloat16 g_Wh[3 * IN_DIM * QKV_COLS];
__device__ __nv_bfloat16 g_Wl[3 * IN_DIM * QKV_COLS];
__device__ __nv_bfloat16 g_Qh[ROWS * QKV_COLS];
__device__ __nv_bfloat16 g_Ql[ROWS * QKV_COLS];
__device__ __nv_bfloat16 g_Kh[ROWS * QKV_COLS];
__device__ __nv_bfloat16 g_Kl[ROWS * QKV_COLS];
__device__ __nv_bfloat16 g_Vh[ROWS * QKV_COLS];
__device__ __nv_bfloat16 g_Vl[ROWS * QKV_COLS];
__device__ float g_kmax[BATCH * NUM_HEADS];

// ---------------------------------------------------------------------------
// helpers
// ---------------------------------------------------------------------------
__device__ __forceinline__ uint32_t smem_u32(const void* p) {
    uint32_t a;
    asm("{ .reg .u64 t; cvta.to.shared.u64 t, %1; cvt.u32.u64 %0, t; }"
        : "=r"(a) : "l"(p));
    return a;
}
__device__ __forceinline__ uint32_t pack_bf2(float a, float b) {
    __nv_bfloat162 t = __floats2bfloat162_rn(a, b);
    return *reinterpret_cast<uint32_t*>(&t);
}
__device__ __forceinline__ float bf_hi(float x) {
    return __bfloat162float(__float2bfloat16_rn(x));
}
__device__ __forceinline__ float2 bf2f(uint32_t u) {
    __nv_bfloat162 b = *reinterpret_cast<__nv_bfloat162*>(&u);
    return __bfloat1622float2(b);
}
__device__ __forceinline__ void ldsm_x4(uint32_t* r, uint32_t addr) {
    asm volatile("ldmatrix.sync.aligned.m8n8.x4.shared.b16 {%0,%1,%2,%3}, [%4];"
        : "=r"(r[0]), "=r"(r[1]), "=r"(r[2]), "=r"(r[3]) : "r"(addr));
}
__device__ __forceinline__ void ldsm_x4_t(uint32_t* r, uint32_t addr) {
    asm volatile("ldmatrix.sync.aligned.m8n8.x4.trans.shared.b16 {%0,%1,%2,%3}, [%4];"
        : "=r"(r[0]), "=r"(r[1]), "=r"(r[2]), "=r"(r[3]) : "r"(addr));
}
__device__ __forceinline__ void mma16816(float* d, const uint32_t* a,
                                         uint32_t b0, uint32_t b1) {
    asm volatile("mma.sync.aligned.m16n8k16.row.col.f32.bf16.bf16.f32 "
        "{%0,%1,%2,%3}, {%4,%5,%6,%7}, {%8,%9}, {%0,%1,%2,%3};"
        : "+f"(d[0]), "+f"(d[1]), "+f"(d[2]), "+f"(d[3])
        : "r"(a[0]), "r"(a[1]), "r"(a[2]), "r"(a[3]), "r"(b0), "r"(b1));
}
__device__ __forceinline__ void split2(float a, float b, uint32_t& hi, uint32_t& lo) {
    float ah = bf_hi(a), bh = bf_hi(b);
    hi = pack_bf2(ah, bh);
    lo = pack_bf2(a - ah, b - bh);
}

// ---------------------------------------------------------------------------
// Kernel 0a: split h (fp32 -> bf16 hi/lo).  524288 float4, grid 2048x256.
// ---------------------------------------------------------------------------
__global__ __launch_bounds__(256)
void split_h_kernel(const float* __restrict__ h)
{
    int idx = blockIdx.x * 256 + threadIdx.x;       // float4 index
    float4 v = ((const float4*)h)[idx];
    uint2 hi, lo;
    split2(v.x, v.y, hi.x, lo.x);
    split2(v.z, v.w, hi.y, lo.y);
    ((uint2*)g_hh)[idx] = hi;
    ((uint2*)g_hl)[idx] = lo;
}

// ---------------------------------------------------------------------------
// Kernel 0b: split W's (fp32 -> bf16 hi/lo), zero g_kmax.
// grid (128, 3), 256 threads; each W is 32768 float4.
// ---------------------------------------------------------------------------
__global__ __launch_bounds__(256)
void split_w_kernel(const float* __restrict__ Wq,
                    const float* __restrict__ Wk,
                    const float* __restrict__ Wv)
{
    const int which = blockIdx.y;
    const float* W = (which == 0) ? Wq : (which == 1) ? Wk : Wv;
    size_t base = (size_t)which * (IN_DIM * QKV_COLS / 4);
    int idx = blockIdx.x * 256 + threadIdx.x;
    float4 v = ((const float4*)W)[idx];
    uint2 hi, lo;
    split2(v.x, v.y, hi.x, lo.x);
    split2(v.z, v.w, hi.y, lo.y);
    ((uint2*)g_Wh)[base + idx] = hi;
    ((uint2*)g_Wl)[base + idx] = lo;
    if (which == 0 && blockIdx.x == 0 && threadIdx.x < BATCH * NUM_HEADS)
        g_kmax[threadIdx.x] = 0.f;
}

// ---------------------------------------------------------------------------
// Kernel 1: QKV projection via mma.sync bf16 3-pass.
// Block 128x128, 8 warps (4m x 2n), warp tile 32x64, BK=32.
// Epilogue: +bias (fp32), x0.125 for Q, split to bf16 hi/lo.
// ---------------------------------------------------------------------------
#define QA_STR 40     // A tile stride (bf16): 32 + 8
#define QB_STR 136    // B tile stride (bf16): 128 + 8

__global__ __launch_bounds__(256, 2)
void qkv_mma_kernel(const float* __restrict__ bq,
                    const float* __restrict__ bk,
                    const float* __restrict__ bv)
{
    __shared__ __nv_bfloat16 sAh[128 * QA_STR];
    __shared__ __nv_bfloat16 sAl[128 * QA_STR];
    __shared__ __nv_bfloat16 sBh[32 * QB_STR];
    __shared__ __nv_bfloat16 sBl[32 * QB_STR];

    const int which = blockIdx.z;
    const __nv_bfloat16* __restrict__ Wh = g_Wh + (size_t)which * IN_DIM * QKV_COLS;
    const __nv_bfloat16* __restrict__ Wl = g_Wl + (size_t)which * IN_DIM * QKV_COLS;
    const float* __restrict__ bias = (which == 0) ? bq : (which == 1) ? bk : bv;
    __nv_bfloat16* __restrict__ Oh = (which == 0) ? g_Qh : (which == 1) ? g_Kh : g_Vh;
    __nv_bfloat16* __restrict__ Ol = (which == 0) ? g_Ql : (which == 1) ? g_Kl : g_Vl;
    const float sc = (which == 0) ? 0.125f : 1.0f;

    const int tid  = threadIdx.x;
    const int w    = tid >> 5;
    const int lane = tid & 31;
    const int warp_m = w >> 1;          // 0..3
    const int warp_n = w & 1;           // 0..1
    const int g  = lane >> 2;
    const int t4 = lane & 3;
    const int row0 = blockIdx.y * 128;
    const int col0 = blockIdx.x * 128;

    const uint32_t aBaseH = smem_u32(sAh);
    const uint32_t aBaseL = smem_u32(sAl);
    const uint32_t bBaseH = smem_u32(sBh);
    const uint32_t bBaseL = smem_u32(sBl);

    float acc[2][8][4] = {};

    for (int kt = 0; kt < IN_DIM / 32; kt++) {
        const int k0 = kt * 32;
        // ---- stage A (128x32) hi/lo ----
        #pragma unroll
        for (int it = 0; it < 2; it++) {
            int lin = it * 256 + tid;
            int r  = lin >> 2;             // 0..127
            int c8 = (lin & 3) * 8;
            size_t go = (size_t)(row0 + r) * IN_DIM + k0 + c8;
            *(uint4*)&sAh[r * QA_STR + c8] = *(const uint4*)&g_hh[go];
            *(uint4*)&sAl[r * QA_STR + c8] = *(const uint4*)&g_hl[go];
        }
        // ---- stage B (32x128) hi/lo ----
        #pragma unroll
        for (int it = 0; it < 2; it++) {
            int lin = it * 256 + tid;
            int r  = lin >> 4;             // 0..31
            int c8 = (lin & 15) * 8;
            size_t go = (size_t)(k0 + r) * QKV_COLS + col0 + c8;
            *(uint4*)&sBh[r * QB_STR + c8] = *(const uint4*)&Wh[go];
            *(uint4*)&sBl[r * QB_STR + c8] = *(const uint4*)&Wl[go];
        }
        __syncthreads();

        // ---- A fragments for both k16 chunks ----
        uint32_t ah[2][2][4], al[2][2][4];
        const int arow = (lane & 7) + 8 * ((lane >> 3) & 1);
        const int acol = 8 * (lane >> 4);
        #pragma unroll
        for (int mi = 0; mi < 2; mi++)
            #pragma unroll
            for (int kk = 0; kk < 2; kk++) {
                uint32_t off = (uint32_t)((32 * warp_m + 16 * mi + arow) * QA_STR
                                          + 16 * kk + acol) * 2;
                ldsm_x4(ah[mi][kk], aBaseH + off);
                ldsm_x4(al[mi][kk], aBaseL + off);
            }

        // ---- B fragments per n8 group; 3-pass mma ----
        const int brow = (lane & 7) + 8 * (lane >> 3);    // 0..31 = k rows
        #pragma unroll
        for (int nj = 0; nj < 8; nj++) {
            uint32_t bh4[4], bl4[4];
            uint32_t off = (uint32_t)(brow * QB_STR + 64 * warp_n + 8 * nj) * 2;
            ldsm_x4_t(bh4, bBaseH + off);
            ldsm_x4_t(bl4, bBaseL + off);
            #pragma unroll
            for (int mi = 0; mi < 2; mi++)
                #pragma unroll
                for (int kk = 0; kk < 2; kk++) {
                    mma16816(acc[mi][nj], ah[mi][kk], bh4[2 * kk], bh4[2 * kk + 1]);
                    mma16816(acc[mi][nj], al[mi][kk], bh4[2 * kk], bh4[2 * kk + 1]);
                    mma16816(acc[mi][nj], ah[mi][kk], bl4[2 * kk], bl4[2 * kk + 1]);
                }
        }
        __syncthreads();
    }

    // ---- epilogue: +bias, scale, split hi/lo, store ----
    #pragma unroll
    for (int nj = 0; nj < 8; nj++) {
        const int cc = col0 + 64 * warp_n + 8 * nj + 2 * t4;
        float2 bb = *(const float2*)&bias[cc];
        #pragma unroll
        for (int mi = 0; mi < 2; mi++) {
            const int r0 = row0 + 32 * warp_m + 16 * mi + g;
            float v0 = (acc[mi][nj][0] + bb.x) * sc;
            float v1 = (acc[mi][nj][1] + bb.y) * sc;
            float v2 = (acc[mi][nj][2] + bb.x) * sc;
            float v3 = (acc[mi][nj][3] + bb.y) * sc;
            uint32_t hi0, lo0, hi1, lo1;
            split2(v0, v1, hi0, lo0);
            split2(v2, v3, hi1, lo1);
            *(uint32_t*)&Oh[(size_t)r0 * QKV_COLS + cc]       = hi0;
            *(uint32_t*)&Ol[(size_t)r0 * QKV_COLS + cc]       = lo0;
            *(uint32_t*)&Oh[(size_t)(r0 + 8) * QKV_COLS + cc] = hi1;
            *(uint32_t*)&Ol[(size_t)(r0 + 8) * QKV_COLS + cc] = lo1;
        }
    }
}

// ---------------------------------------------------------------------------
// Kernel 1b: max_k |k|^2 per (batch, head). grid (64, 8) x 128 thr, atomicMax.
// ---------------------------------------------------------------------------
__global__ __launch_bounds__(128)
void kmax_kernel()
{
    const int bh = blockIdx.x;
    const int r  = blockIdx.y * 128 + threadIdx.x;
    const __nv_bfloat16* Kh = g_Kh + ((size_t)(bh >> 3) * SEQ + r) * QKV_COLS + (bh & 7) * OUT_DIM;
    const __nv_bfloat16* Kl = g_Kl + ((size_t)(bh >> 3) * SEQ + r) * QKV_COLS + (bh & 7) * OUT_DIM;

    float ss = 0.f;
    #pragma unroll
    for (int c = 0; c < 8; c++) {
        uint4 uh = *(const uint4*)&Kh[c * 8];
        uint4 ul = *(const uint4*)&Kl[c * 8];
        const uint32_t* ph = (const uint32_t*)&uh;
        const uint32_t* pl = (const uint32_t*)&ul;
        #pragma unroll
        for (int q = 0; q < 4; q++) {
            float2 fh = bf2f(ph[q]), fl = bf2f(pl[q]);
            float a = fh.x + fl.x, b = fh.y + fl.y;
            ss = fmaf(a, a, ss); ss = fmaf(b, b, ss);
        }
    }
    #pragma unroll
    for (int off = 16; off >= 1; off >>= 1)
        ss = fmaxf(ss, __shfl_xor_sync(0xffffffffu, ss, off));
    if ((threadIdx.x & 31) == 0)
        atomicMax((unsigned int*)&g_kmax[bh], __float_as_uint(ss));
}

// ---------------------------------------------------------------------------
// Kernel 2: mma.sync bf16-split flash attention (unchanged from R7).
// ---------------------------------------------------------------------------
#define TSTR 72
#define TILE_E (64 * TSTR)

__global__ __launch_bounds__(128, 2)
void attn_mma_kernel(const int* __restrict__ adj, float* __restrict__ out)
{
    extern __shared__ __nv_bfloat16 sm[];
    __nv_bfloat16* sQh = sm;
    __nv_bfloat16* sQl = sQh + TILE_E;
    __nv_bfloat16* sKh = sQl + TILE_E;
    __nv_bfloat16* sKl = sKh + TILE_E;
    __nv_bfloat16* sVh = sKl + TILE_E;
    __nv_bfloat16* sVl = sVh + TILE_E;
    float* sM = (float*)(sVl + TILE_E);

    const int b  = blockIdx.z;
    const int hd = blockIdx.y;
    const int q0 = blockIdx.x * 64;
    const int tid  = threadIdx.x;
    const int w    = tid >> 5;
    const int lane = tid & 31;
    const int g  = lane >> 2;
    const int t4 = lane & 3;

    const size_t bN  = (size_t)b * SEQ;
    const int hdo = hd * OUT_DIM;

    #pragma unroll
    for (int it = 0; it < 4; it++) {
        int lin = it * 128 + tid;
        int r  = lin >> 3;
        int c8 = (lin & 7) * 8;
        *(uint4*)&sQh[r * TSTR + c8] =
            *(const uint4*)&g_Qh[(bN + q0 + r) * QKV_COLS + hdo + c8];
        *(uint4*)&sQl[r * TSTR + c8] =
            *(const uint4*)&g_Ql[(bN + q0 + r) * QKV_COLS + hdo + c8];
    }
    __syncthreads();

    const float kmax2 = g_kmax[b * NUM_HEADS + hd];
    if (tid < 64) {
        float ss = 0.f;
        #pragma unroll
        for (int c = 0; c < 8; c++) {
            uint4 uh = *(const uint4*)&sQh[tid * TSTR + c * 8];
            uint4 ul = *(const uint4*)&sQl[tid * TSTR + c * 8];
            const uint32_t* ph = (const uint32_t*)&uh;
            const uint32_t* pl = (const uint32_t*)&ul;
            #pragma unroll
            for (int q = 0; q < 4; q++) {
                float2 fh = bf2f(ph[q]), fl = bf2f(pl[q]);
                float a = fh.x + fl.x, c2 = fh.y + fl.y;
                ss = fmaf(a, a, ss); ss = fmaf(c2, c2, ss);
            }
        }
        sM[tid] = sqrtf(ss * kmax2);
    }
    __syncthreads();

    const uint32_t qbase_h = smem_u32(sQh);
    const uint32_t qbase_l = smem_u32(sQl);
    uint32_t qh[4][4], ql[4][4];
    {
        int row = 16 * w + (lane & 7) + 8 * ((lane >> 3) & 1);
        int dof = 8 * (lane >> 4);
        #pragma unroll
        for (int kt = 0; kt < 4; kt++) {
            uint32_t off = (uint32_t)(row * TSTR + 16 * kt + dof) * 2;
            ldsm_x4(qh[kt], qbase_h + off);
            ldsm_x4(ql[kt], qbase_l + off);
        }
    }
    const float mg = sM[16 * w + g];
    const float m2 = sM[16 * w + g + 8];

    const uint32_t kbase_h = smem_u32(sKh);
    const uint32_t kbase_l = smem_u32(sKl);
    const uint32_t vbase_h = smem_u32(sVh);
    const uint32_t vbase_l = smem_u32(sVl);

    float o[8][4] = {};
    float lg = 0.f, l2 = 0.f;

    for (int t = 0; t < SEQ / 64; t++) {
        const int m0 = t * 64;

        #pragma unroll
        for (int it = 0; it < 4; it++) {
            int lin = it * 128 + tid;
            int r  = lin >> 3;
            int c8 = (lin & 7) * 8;
            size_t gofs = (bN + m0 + r) * QKV_COLS + hdo + c8;
            int sofs = r * TSTR + c8;
            *(uint4*)&sKh[sofs] = *(const uint4*)&g_Kh[gofs];
            *(uint4*)&sKl[sofs] = *(const uint4*)&g_Kl[gofs];
            *(uint4*)&sVh[sofs] = *(const uint4*)&g_Vh[gofs];
            *(uint4*)&sVl[sofs] = *(const uint4*)&g_Vl[gofs];
        }
        __syncthreads();

        float pv[8][4];
        const int krow = (lane & 7);
        const int kdof = 8 * (lane >> 3);
        #pragma unroll
        for (int j = 0; j < 8; j++) {
            uint32_t bh[8], bl[8];
            uint32_t roff = (uint32_t)((8 * j + krow) * TSTR + kdof) * 2;
            ldsm_x4(bh + 0, kbase_h + roff);
            ldsm_x4(bh + 4, kbase_h + roff + 64);
            ldsm_x4(bl + 0, kbase_l + roff);
            ldsm_x4(bl + 4, kbase_l + roff + 64);
            float d[4] = {};
            #pragma unroll
            for (int kt = 0; kt < 4; kt++) {
                int hi2 = kt >> 1, oo = (kt & 1) * 2;
                mma16816(d, qh[kt], bh[4 * hi2 + oo], bh[4 * hi2 + oo + 1]);
            }
            #pragma unroll
            for (int kt = 0; kt < 4; kt++) {
                int hi2 = kt >> 1, oo = (kt & 1) * 2;
                mma16816(d, ql[kt], bh[4 * hi2 + oo], bh[4 * hi2 + oo + 1]);
            }
            #pragma unroll
            for (int kt = 0; kt < 4; kt++) {
                int hi2 = kt >> 1, oo = (kt & 1) * 2;
                mma16816(d, qh[kt], bl[4 * hi2 + oo], bl[4 * hi2 + oo + 1]);
            }
            pv[j][0] = d[0]; pv[j][1] = d[1]; pv[j][2] = d[2]; pv[j][3] = d[3];
        }

        const int r1 = q0 + 16 * w + g;
        #pragma unroll
        for (int j = 0; j < 8; j++) {
            int cc = m0 + 8 * j + 2 * t4;
            int2 a0 = *(const int2*)&adj[(size_t)r1 * SEQ + cc];
            int2 a1 = *(const int2*)&adj[(size_t)(r1 + 8) * SEQ + cc];
            float p0 = a0.x ? __expf(pv[j][0] - mg) : 0.f;
            float p1 = a0.y ? __expf(pv[j][1] - mg) : 0.f;
            float p2 = a1.x ? __expf(pv[j][2] - m2) : 0.f;
            float p3 = a1.y ? __expf(pv[j][3] - m2) : 0.f;
            lg += p0 + p1;
            l2 += p2 + p3;
            pv[j][0] = p0; pv[j][1] = p1; pv[j][2] = p2; pv[j][3] = p3;
        }

        uint32_t ph[4][4], pl[4][4];
        #pragma unroll
        for (int kt = 0; kt < 4; kt++) {
            const float* e0 = pv[2 * kt];
            const float* e1 = pv[2 * kt + 1];
            split2(e0[0], e0[1], ph[kt][0], pl[kt][0]);
            split2(e0[2], e0[3], ph[kt][1], pl[kt][1]);
            split2(e1[0], e1[1], ph[kt][2], pl[kt][2]);
            split2(e1[2], e1[3], ph[kt][3], pl[kt][3]);
        }

        const int vrow = 8 * (lane >> 3) + (lane & 7);
        #pragma unroll
        for (int j = 0; j < 8; j++) {
            uint32_t bh[8], bl[8];
            uint32_t c2 = (uint32_t)(8 * j) * 2;
            uint32_t r0 = (uint32_t)(vrow * TSTR) * 2 + c2;
            uint32_t r32 = (uint32_t)((vrow + 32) * TSTR) * 2 + c2;
            ldsm_x4_t(bh + 0, vbase_h + r0);
            ldsm_x4_t(bh + 4, vbase_h + r32);
            ldsm_x4_t(bl + 0, vbase_l + r0);
            ldsm_x4_t(bl + 4, vbase_l + r32);
            #pragma unroll
            for (int kt = 0; kt < 4; kt++) {
                int hi2 = kt >> 1, oo = (kt & 1) * 2;
                uint32_t vb0 = bh[4 * hi2 + oo], vb1 = bh[4 * hi2 + oo + 1];
                uint32_t wb0 = bl[4 * hi2 + oo], wb1 = bl[4 * hi2 + oo + 1];
                mma16816(o[j], ph[kt], vb0, vb1);
                mma16816(o[j], pl[kt], vb0, vb1);
                mma16816(o[j], ph[kt], wb0, wb1);
            }
        }
        __syncthreads();
    }

    lg += __shfl_xor_sync(0xffffffffu, lg, 1);
    lg += __shfl_xor_sync(0xffffffffu, lg, 2);
    l2 += __shfl_xor_sync(0xffffffffu, l2, 1);
    l2 += __shfl_xor_sync(0xffffffffu, l2, 2);
    const float invg = 1.0f / lg;
    const float inv2 = 1.0f / l2;

    const int r1 = q0 + 16 * w + g;
    #pragma unroll
    for (int j = 0; j < 8; j++) {
        int cc = hdo + 8 * j + 2 * t4;
        *(float2*)&out[(bN + r1) * QKV_COLS + cc] =
            make_float2(o[j][0] * invg, o[j][1] * invg);
        *(float2*)&out[(bN + r1 + 8) * QKV_COLS + cc] =
            make_float2(o[j][2] * inv2, o[j][3] * inv2);
    }
}

// ---------------------------------------------------------------------------
// Launch
// ---------------------------------------------------------------------------
extern "C" void kernel_launch(void* const* d_in, const int* in_sizes, int n_in,
                              void* d_out, int out_size)
{
    const int*   adj = (const int*)  d_in[0];
    const float* h   = (const float*)d_in[1];
    const float* Wq  = (const float*)d_in[2];
    const float* bq  = (const float*)d_in[3];
    const float* Wk  = (const float*)d_in[4];
    const float* bk  = (const float*)d_in[5];
    const float* Wv  = (const float*)d_in[6];
    const float* bv  = (const float*)d_in[7];
    float* out = (float*)d_out;

    split_h_kernel<<<ROWS * IN_DIM / 4 / 256, 256>>>(h);
    split_w_kernel<<<dim3(IN_DIM * QKV_COLS / 4 / 256, 3), 256>>>(Wq, Wk, Wv);
    qkv_mma_kernel<<<dim3(QKV_COLS / 128, ROWS / 128, 3), 256>>>(bq, bk, bv);
    kmax_kernel<<<dim3(BATCH * NUM_HEADS, SEQ / 128), 128>>>();

    const int smem_bytes = 6 * TILE_E * 2 + 64 * 4;   // 55,552 B
    static bool attr_set = false;
    if (!attr_set) {
        cudaFuncSetAttribute(attn_mma_kernel,
                             cudaFuncAttributeMaxDynamicSharedMemorySize, smem_bytes);
        attr_set = true;
    }
    attn_mma_kernel<<<dim3(SEQ / 64, NUM_HEADS, BATCH), 128, smem_bytes>>>(adj, out);
}

// round 9
// speedup vs baseline: 6.4011x; 1.3619x over previous
#include <cuda_runtime.h>
#include <cuda_fp16.h>
#include <math.h>
#include <stdint.h>

#define IN_DIM   256
#define OUT_DIM  64
#define NUM_HEADS 8
#define BATCH    8
#define SEQ      1024
#define QKV_COLS (OUT_DIM * NUM_HEADS)   // 512
#define ROWS     (BATCH * SEQ)           // 8192

// fp16 hi/lo split tensors (Q pre-scaled by 0.125). K/V need hi only.
__device__ __half g_Wh[3 * IN_DIM * QKV_COLS];
__device__ __half g_Wl[3 * IN_DIM * QKV_COLS];
__device__ __half g_Qh[ROWS * QKV_COLS];
__device__ __half g_Ql[ROWS * QKV_COLS];
__device__ __half g_Kh[ROWS * QKV_COLS];
__device__ __half g_Vh[ROWS * QKV_COLS];
__device__ float g_kmax[BATCH * NUM_HEADS];

// ---------------------------------------------------------------------------
// helpers
// ---------------------------------------------------------------------------
__device__ __forceinline__ uint32_t smem_u32(const void* p) {
    uint32_t a;
    asm("{ .reg .u64 t; cvta.to.shared.u64 t, %1; cvt.u32.u64 %0, t; }"
        : "=r"(a) : "l"(p));
    return a;
}
__device__ __forceinline__ uint32_t pack_hf2(float a, float b) {
    __half2 t = __floats2half2_rn(a, b);
    return *reinterpret_cast<uint32_t*>(&t);
}
__device__ __forceinline__ float2 hf2f(uint32_t u) {
    __half2 h = *reinterpret_cast<__half2*>(&u);
    return __half22float2(h);
}
__device__ __forceinline__ void split2(float a, float b, uint32_t& hi, uint32_t& lo) {
    float ah = __half2float(__float2half_rn(a));
    float bh = __half2float(__float2half_rn(b));
    hi = pack_hf2(ah, bh);
    lo = pack_hf2(a - ah, b - bh);
}
__device__ __forceinline__ void ldsm_x4(uint32_t* r, uint32_t addr) {
    asm volatile("ldmatrix.sync.aligned.m8n8.x4.shared.b16 {%0,%1,%2,%3}, [%4];"
        : "=r"(r[0]), "=r"(r[1]), "=r"(r[2]), "=r"(r[3]) : "r"(addr));
}
__device__ __forceinline__ void ldsm_x4_t(uint32_t* r, uint32_t addr) {
    asm volatile("ldmatrix.sync.aligned.m8n8.x4.trans.shared.b16 {%0,%1,%2,%3}, [%4];"
        : "=r"(r[0]), "=r"(r[1]), "=r"(r[2]), "=r"(r[3]) : "r"(addr));
}
__device__ __forceinline__ void mma16816(float* d, const uint32_t* a,
                                         uint32_t b0, uint32_t b1) {
    asm volatile("mma.sync.aligned.m16n8k16.row.col.f32.f16.f16.f32 "
        "{%0,%1,%2,%3}, {%4,%5,%6,%7}, {%8,%9}, {%0,%1,%2,%3};"
        : "+f"(d[0]), "+f"(d[1]), "+f"(d[2]), "+f"(d[3])
        : "r"(a[0]), "r"(a[1]), "r"(a[2]), "r"(a[3]), "r"(b0), "r"(b1));
}

// ---------------------------------------------------------------------------
// Kernel 0: split W's (fp32 -> fp16 hi/lo), zero g_kmax.
// ---------------------------------------------------------------------------
__global__ __launch_bounds__(256)
void split_w_kernel(const float* __restrict__ Wq,
                    const float* __restrict__ Wk,
                    const float* __restrict__ Wv)
{
    const int which = blockIdx.y;
    const float* W = (which == 0) ? Wq : (which == 1) ? Wk : Wv;
    size_t base = (size_t)which * (IN_DIM * QKV_COLS / 4);
    int idx = blockIdx.x * 256 + threadIdx.x;
    float4 v = ((const float4*)W)[idx];
    uint2 hi, lo;
    split2(v.x, v.y, hi.x, lo.x);
    split2(v.z, v.w, hi.y, lo.y);
    ((uint2*)g_Wh)[base + idx] = hi;
    ((uint2*)g_Wl)[base + idx] = lo;
    if (which == 0 && blockIdx.x == 0 && threadIdx.x < BATCH * NUM_HEADS)
        g_kmax[threadIdx.x] = 0.f;
}

// ---------------------------------------------------------------------------
// Kernel 1: QKV projection via mma.sync fp16 3-pass.
// Block 128x128, 8 warps (4m x 2n), warp tile 32x64, BK=32.
// A staged directly from fp32 h (split in-kernel).  Epilogue: +bias,
// x0.125 for Q, split Q hi/lo, store K/V hi only, K row-norm atomicMax.
// ---------------------------------------------------------------------------
#define QA_STR 40
#define QB_STR 136

__global__ __launch_bounds__(256, 2)
void qkv_mma_kernel(const float* __restrict__ h,
                    const float* __restrict__ bq,
                    const float* __restrict__ bk,
                    const float* __restrict__ bv)
{
    __shared__ __half sAh[128 * QA_STR];
    __shared__ __half sAl[128 * QA_STR];
    __shared__ __half sBh[32 * QB_STR];
    __shared__ __half sBl[32 * QB_STR];

    const int which = blockIdx.z;
    const __half* __restrict__ Wh = g_Wh + (size_t)which * IN_DIM * QKV_COLS;
    const __half* __restrict__ Wl = g_Wl + (size_t)which * IN_DIM * QKV_COLS;
    const float* __restrict__ bias = (which == 0) ? bq : (which == 1) ? bk : bv;
    __half* __restrict__ Oh = (which == 0) ? g_Qh : (which == 1) ? g_Kh : g_Vh;
    const float sc = (which == 0) ? 0.125f : 1.0f;

    const int tid  = threadIdx.x;
    const int w    = tid >> 5;
    const int lane = tid & 31;
    const int warp_m = w >> 1;
    const int warp_n = w & 1;
    const int g  = lane >> 2;
    const int t4 = lane & 3;
    const int row0 = blockIdx.y * 128;
    const int col0 = blockIdx.x * 128;

    const uint32_t aBaseH = smem_u32(sAh);
    const uint32_t aBaseL = smem_u32(sAl);
    const uint32_t bBaseH = smem_u32(sBh);
    const uint32_t bBaseL = smem_u32(sBl);

    float acc[2][8][4] = {};

    for (int kt = 0; kt < IN_DIM / 32; kt++) {
        const int k0 = kt * 32;
        // ---- stage A (128x32): fp32 h -> fp16 hi/lo in-kernel ----
        #pragma unroll
        for (int it = 0; it < 2; it++) {
            int lin = it * 256 + tid;
            int r  = lin >> 2;             // 0..127
            int c8 = (lin & 3) * 8;
            const float* src = &h[(size_t)(row0 + r) * IN_DIM + k0 + c8];
            float4 v0 = *(const float4*)src;
            float4 v1 = *(const float4*)(src + 4);
            uint4 hi, lo;
            split2(v0.x, v0.y, hi.x, lo.x);
            split2(v0.z, v0.w, hi.y, lo.y);
            split2(v1.x, v1.y, hi.z, lo.z);
            split2(v1.z, v1.w, hi.w, lo.w);
            *(uint4*)&sAh[r * QA_STR + c8] = hi;
            *(uint4*)&sAl[r * QA_STR + c8] = lo;
        }
        // ---- stage B (32x128) hi/lo from split W ----
        #pragma unroll
        for (int it = 0; it < 2; it++) {
            int lin = it * 256 + tid;
            int r  = lin >> 4;             // 0..31
            int c8 = (lin & 15) * 8;
            size_t go = (size_t)(k0 + r) * QKV_COLS + col0 + c8;
            *(uint4*)&sBh[r * QB_STR + c8] = *(const uint4*)&Wh[go];
            *(uint4*)&sBl[r * QB_STR + c8] = *(const uint4*)&Wl[go];
        }
        __syncthreads();

        uint32_t ah[2][2][4], al[2][2][4];
        const int arow = (lane & 7) + 8 * ((lane >> 3) & 1);
        const int acol = 8 * (lane >> 4);
        #pragma unroll
        for (int mi = 0; mi < 2; mi++)
            #pragma unroll
            for (int kk = 0; kk < 2; kk++) {
                uint32_t off = (uint32_t)((32 * warp_m + 16 * mi + arow) * QA_STR
                                          + 16 * kk + acol) * 2;
                ldsm_x4(ah[mi][kk], aBaseH + off);
                ldsm_x4(al[mi][kk], aBaseL + off);
            }

        const int brow = (lane & 7) + 8 * (lane >> 3);
        #pragma unroll
        for (int nj = 0; nj < 8; nj++) {
            uint32_t bh4[4], bl4[4];
            uint32_t off = (uint32_t)(brow * QB_STR + 64 * warp_n + 8 * nj) * 2;
            ldsm_x4_t(bh4, bBaseH + off);
            ldsm_x4_t(bl4, bBaseL + off);
            #pragma unroll
            for (int mi = 0; mi < 2; mi++)
                #pragma unroll
                for (int kk = 0; kk < 2; kk++) {
                    mma16816(acc[mi][nj], ah[mi][kk], bh4[2 * kk], bh4[2 * kk + 1]);
                    mma16816(acc[mi][nj], al[mi][kk], bh4[2 * kk], bh4[2 * kk + 1]);
                    mma16816(acc[mi][nj], ah[mi][kk], bl4[2 * kk], bl4[2 * kk + 1]);
                }
        }
        __syncthreads();
    }

    // ---- epilogue ----
    float ssA[2] = {0.f, 0.f}, ssB[2] = {0.f, 0.f};
    #pragma unroll
    for (int nj = 0; nj < 8; nj++) {
        const int cc = col0 + 64 * warp_n + 8 * nj + 2 * t4;
        float2 bb = *(const float2*)&bias[cc];
        #pragma unroll
        for (int mi = 0; mi < 2; mi++) {
            const int r0 = row0 + 32 * warp_m + 16 * mi + g;
            float v0 = (acc[mi][nj][0] + bb.x) * sc;
            float v1 = (acc[mi][nj][1] + bb.y) * sc;
            float v2 = (acc[mi][nj][2] + bb.x) * sc;
            float v3 = (acc[mi][nj][3] + bb.y) * sc;
            ssA[mi] = fmaf(v0, v0, ssA[mi]); ssA[mi] = fmaf(v1, v1, ssA[mi]);
            ssB[mi] = fmaf(v2, v2, ssB[mi]); ssB[mi] = fmaf(v3, v3, ssB[mi]);
            uint32_t hi0, lo0, hi1, lo1;
            split2(v0, v1, hi0, lo0);
            split2(v2, v3, hi1, lo1);
            *(uint32_t*)&Oh[(size_t)r0 * QKV_COLS + cc]       = hi0;
            *(uint32_t*)&Oh[(size_t)(r0 + 8) * QKV_COLS + cc] = hi1;
            if (which == 0) {
                *(uint32_t*)&g_Ql[(size_t)r0 * QKV_COLS + cc]       = lo0;
                *(uint32_t*)&g_Ql[(size_t)(r0 + 8) * QKV_COLS + cc] = lo1;
            }
        }
    }

    // ---- K row-norm max -> g_kmax (warp covers 32 rows x one head segment) ----
    if (which == 1) {
        float s0 = ssA[0], s1 = ssB[0], s2 = ssA[1], s3 = ssB[1];
        #pragma unroll
        for (int off = 1; off <= 2; off <<= 1) {
            s0 += __shfl_xor_sync(0xffffffffu, s0, off);
            s1 += __shfl_xor_sync(0xffffffffu, s1, off);
            s2 += __shfl_xor_sync(0xffffffffu, s2, off);
            s3 += __shfl_xor_sync(0xffffffffu, s3, off);
        }
        float mx = fmaxf(fmaxf(s0, s1), fmaxf(s2, s3));
        #pragma unroll
        for (int off = 4; off <= 16; off <<= 1)
            mx = fmaxf(mx, __shfl_xor_sync(0xffffffffu, mx, off));
        if (lane == 0) {
            int bh = (row0 >> 10) * NUM_HEADS + ((col0 + 64 * warp_n) >> 6);
            atomicMax((unsigned int*)&g_kmax[bh], __float_as_uint(mx));
        }
    }
}

// ---------------------------------------------------------------------------
// Kernel 2: mma.sync fp16 2-pass flash attention, static max.
// Block = (64-query tile, head, batch), 4 warps.  K/V hi-only.
// ---------------------------------------------------------------------------
#define TSTR 72
#define TILE_E (64 * TSTR)

__global__ __launch_bounds__(128, 3)
void attn_mma_kernel(const int* __restrict__ adj, float* __restrict__ out)
{
    extern __shared__ __half sm[];
    __half* sQh = sm;
    __half* sQl = sQh + TILE_E;
    __half* sKh = sQl + TILE_E;
    __half* sVh = sKh + TILE_E;
    float* sM = (float*)(sVh + TILE_E);

    const int b  = blockIdx.z;
    const int hd = blockIdx.y;
    const int q0 = blockIdx.x * 64;
    const int tid  = threadIdx.x;
    const int w    = tid >> 5;
    const int lane = tid & 31;
    const int g  = lane >> 2;
    const int t4 = lane & 3;

    const size_t bN  = (size_t)b * SEQ;
    const int hdo = hd * OUT_DIM;

    #pragma unroll
    for (int it = 0; it < 4; it++) {
        int lin = it * 128 + tid;
        int r  = lin >> 3;
        int c8 = (lin & 7) * 8;
        *(uint4*)&sQh[r * TSTR + c8] =
            *(const uint4*)&g_Qh[(bN + q0 + r) * QKV_COLS + hdo + c8];
        *(uint4*)&sQl[r * TSTR + c8] =
            *(const uint4*)&g_Ql[(bN + q0 + r) * QKV_COLS + hdo + c8];
    }
    __syncthreads();

    const float kmax2 = g_kmax[b * NUM_HEADS + hd];
    if (tid < 64) {
        float ss = 0.f;
        #pragma unroll
        for (int c = 0; c < 8; c++) {
            uint4 uh = *(const uint4*)&sQh[tid * TSTR + c * 8];
            uint4 ul = *(const uint4*)&sQl[tid * TSTR + c * 8];
            const uint32_t* ph = (const uint32_t*)&uh;
            const uint32_t* pl = (const uint32_t*)&ul;
            #pragma unroll
            for (int q = 0; q < 4; q++) {
                float2 fh = hf2f(ph[q]), fl = hf2f(pl[q]);
                float a = fh.x + fl.x, c2 = fh.y + fl.y;
                ss = fmaf(a, a, ss); ss = fmaf(c2, c2, ss);
            }
        }
        sM[tid] = sqrtf(ss * kmax2);
    }
    __syncthreads();

    const uint32_t qbase_h = smem_u32(sQh);
    const uint32_t qbase_l = smem_u32(sQl);
    uint32_t qh[4][4], ql[4][4];
    {
        int row = 16 * w + (lane & 7) + 8 * ((lane >> 3) & 1);
        int dof = 8 * (lane >> 4);
        #pragma unroll
        for (int kt = 0; kt < 4; kt++) {
            uint32_t off = (uint32_t)(row * TSTR + 16 * kt + dof) * 2;
            ldsm_x4(qh[kt], qbase_h + off);
            ldsm_x4(ql[kt], qbase_l + off);
        }
    }
    const float mg = sM[16 * w + g];
    const float m2 = sM[16 * w + g + 8];

    const uint32_t kbase_h = smem_u32(sKh);
    const uint32_t vbase_h = smem_u32(sVh);

    float o[8][4] = {};
    float lg = 0.f, l2 = 0.f;

    for (int t = 0; t < SEQ / 64; t++) {
        const int m0 = t * 64;

        #pragma unroll
        for (int it = 0; it < 4; it++) {
            int lin = it * 128 + tid;
            int r  = lin >> 3;
            int c8 = (lin & 7) * 8;
            size_t gofs = (bN + m0 + r) * QKV_COLS + hdo + c8;
            int sofs = r * TSTR + c8;
            *(uint4*)&sKh[sofs] = *(const uint4*)&g_Kh[gofs];
            *(uint4*)&sVh[sofs] = *(const uint4*)&g_Vh[gofs];
        }
        __syncthreads();

        // ---- QK^T: 2 passes (q_hi + q_lo) x k_hi ----
        float pv[8][4];
        const int krow = (lane & 7);
        const int kdof = 8 * (lane >> 3);
        #pragma unroll
        for (int j = 0; j < 8; j++) {
            uint32_t bh[8];
            uint32_t roff = (uint32_t)((8 * j + krow) * TSTR + kdof) * 2;
            ldsm_x4(bh + 0, kbase_h + roff);
            ldsm_x4(bh + 4, kbase_h + roff + 64);
            float d[4] = {};
            #pragma unroll
            for (int kt = 0; kt < 4; kt++) {
                int hi2 = kt >> 1, oo = (kt & 1) * 2;
                mma16816(d, qh[kt], bh[4 * hi2 + oo], bh[4 * hi2 + oo + 1]);
            }
            #pragma unroll
            for (int kt = 0; kt < 4; kt++) {
                int hi2 = kt >> 1, oo = (kt & 1) * 2;
                mma16816(d, ql[kt], bh[4 * hi2 + oo], bh[4 * hi2 + oo + 1]);
            }
            pv[j][0] = d[0]; pv[j][1] = d[1]; pv[j][2] = d[2]; pv[j][3] = d[3];
        }

        const int r1 = q0 + 16 * w + g;
        #pragma unroll
        for (int j = 0; j < 8; j++) {
            int cc = m0 + 8 * j + 2 * t4;
            int2 a0 = *(const int2*)&adj[(size_t)r1 * SEQ + cc];
            int2 a1 = *(const int2*)&adj[(size_t)(r1 + 8) * SEQ + cc];
            float p0 = a0.x ? __expf(pv[j][0] - mg) : 0.f;
            float p1 = a0.y ? __expf(pv[j][1] - mg) : 0.f;
            float p2 = a1.x ? __expf(pv[j][2] - m2) : 0.f;
            float p3 = a1.y ? __expf(pv[j][3] - m2) : 0.f;
            lg += p0 + p1;
            l2 += p2 + p3;
            pv[j][0] = p0; pv[j][1] = p1; pv[j][2] = p2; pv[j][3] = p3;
        }

        uint32_t ph[4][4], pl[4][4];
        #pragma unroll
        for (int kt = 0; kt < 4; kt++) {
            const float* e0 = pv[2 * kt];
            const float* e1 = pv[2 * kt + 1];
            split2(e0[0], e0[1], ph[kt][0], pl[kt][0]);
            split2(e0[2], e0[3], ph[kt][1], pl[kt][1]);
            split2(e1[0], e1[1], ph[kt][2], pl[kt][2]);
            split2(e1[2], e1[3], ph[kt][3], pl[kt][3]);
        }

        // ---- PV: 2 passes (p_hi + p_lo) x v_hi ----
        const int vrow = 8 * (lane >> 3) + (lane & 7);
        #pragma unroll
        for (int j = 0; j < 8; j++) {
            uint32_t bh[8];
            uint32_t c2 = (uint32_t)(8 * j) * 2;
            uint32_t r0 = (uint32_t)(vrow * TSTR) * 2 + c2;
            uint32_t r32 = (uint32_t)((vrow + 32) * TSTR) * 2 + c2;
            ldsm_x4_t(bh + 0, vbase_h + r0);
            ldsm_x4_t(bh + 4, vbase_h + r32);
            #pragma unroll
            for (int kt = 0; kt < 4; kt++) {
                int hi2 = kt >> 1, oo = (kt & 1) * 2;
                uint32_t vb0 = bh[4 * hi2 + oo], vb1 = bh[4 * hi2 + oo + 1];
                mma16816(o[j], ph[kt], vb0, vb1);
                mma16816(o[j], pl[kt], vb0, vb1);
            }
        }
        __syncthreads();
    }

    lg += __shfl_xor_sync(0xffffffffu, lg, 1);
    lg += __shfl_xor_sync(0xffffffffu, lg, 2);
    l2 += __shfl_xor_sync(0xffffffffu, l2, 1);
    l2 += __shfl_xor_sync(0xffffffffu, l2, 2);
    const float invg = 1.0f / lg;
    const float inv2 = 1.0f / l2;

    const int r1 = q0 + 16 * w + g;
    #pragma unroll
    for (int j = 0; j < 8; j++) {
        int cc = hdo + 8 * j + 2 * t4;
        *(float2*)&out[(bN + r1) * QKV_COLS + cc] =
            make_float2(o[j][0] * invg, o[j][1] * invg);
        *(float2*)&out[(bN + r1 + 8) * QKV_COLS + cc] =
            make_float2(o[j][2] * inv2, o[j][3] * inv2);
    }
}

// ---------------------------------------------------------------------------
// Launch
// ---------------------------------------------------------------------------
extern "C" void kernel_launch(void* const* d_in, const int* in_sizes, int n_in,
                              void* d_out, int out_size)
{
    const int*   adj = (const int*)  d_in[0];
    const float* h   = (const float*)d_in[1];
    const float* Wq  = (const float*)d_in[2];
    const float* bq  = (const float*)d_in[3];
    const float* Wk  = (const float*)d_in[4];
    const float* bk  = (const float*)d_in[5];
    const float* Wv  = (const float*)d_in[6];
    const float* bv  = (const float*)d_in[7];
    float* out = (float*)d_out;

    split_w_kernel<<<dim3(IN_DIM * QKV_COLS / 4 / 256, 3), 256>>>(Wq, Wk, Wv);
    qkv_mma_kernel<<<dim3(QKV_COLS / 128, ROWS / 128, 3), 256>>>(h, bq, bk, bv);

    const int smem_bytes = 4 * TILE_E * 2 + 64 * 4;   // 37,120 B
    static bool attr_set = false;
    if (!attr_set) {
        cudaFuncSetAttribute(attn_mma_kernel,
                             cudaFuncAttributeMaxDynamicSharedMemorySize, smem_bytes);
        attr_set = true;
    }
    attn_mma_kernel<<<dim3(SEQ / 64, NUM_HEADS, BATCH), 128, smem_bytes>>>(adj, out);
}